// round 2
// baseline (speedup 1.0000x reference)
#include <cuda_runtime.h>
#include <cstdint>

// Problem dims (fixed by the dataset)
#define TOKENS 8192
#define IN_F   4096
#define OUT_F  4096

constexpr int BM = 128;
constexpr int BN = 128;
constexpr int BK = 64;
constexpr int THREADS = 256;
constexpr int SSTRIDE = 80;   // bytes per smem tile row (64 data + 16 pad -> conflict-free)

// Scratch for packed int8 operands (inputs arrive widened to int32).
__device__ int8_t g_packedX[(size_t)TOKENS * IN_F];
__device__ int8_t g_packedW[(size_t)OUT_F * IN_F];

// ---------------- pack kernels: int32 -> int8 ----------------
__global__ void __launch_bounds__(256)
pack_kernel(const int* __restrict__ src, uint32_t* __restrict__ dst, int n_words)
{
    int i = blockIdx.x * blockDim.x + threadIdx.x;
    if (i >= n_words) return;
    int4 v = ((const int4*)src)[i];
    uint32_t p = (v.x & 0xff) | ((v.y & 0xff) << 8) |
                 ((v.z & 0xff) << 16) | ((uint32_t)v.w << 24);
    dst[i] = p;
}

// ---------------- helpers ----------------
__device__ __forceinline__ uint32_t smem_u32(const void* p) {
    return (uint32_t)__cvta_generic_to_shared(p);
}

__device__ __forceinline__ void cp_async16(uint32_t smem_addr, const void* gmem) {
    asm volatile("cp.async.cg.shared.global [%0], [%1], 16;\n"
                 :: "r"(smem_addr), "l"(gmem) : "memory");
}

__device__ __forceinline__ float quantize_gelu(int acc, float biasv, float a, float b) {
    float y = fmaf(a, (float)acc, biasv);
    // exact GeLU: 0.5*y*(1+erf(y/sqrt(2)))
    float g = 0.5f * y * (1.0f + erff(y * 0.70710678118654752440f));
    int q = __float2int_rn(g * b);       // round-to-nearest-even, matches jnp.rint
    q = max(-128, min(127, q));
    return (float)q;
}

// ---------------- main GEMM + fused epilogue ----------------
__global__ void __launch_bounds__(THREADS, 2)
w8a8_gelu_q_kernel(const float*  __restrict__ bias,
                   const float*  __restrict__ pa,
                   const float*  __restrict__ pb,
                   float* __restrict__ out)
{
    __shared__ __align__(16) int8_t sA[2][BM * SSTRIDE];
    __shared__ __align__(16) int8_t sB[2][BN * SSTRIDE];

    const int tid    = threadIdx.x;
    const int lane   = tid & 31;
    const int warp   = tid >> 5;
    const int warp_m = warp >> 2;   // 0..1 -> 64 rows each
    const int warp_n = warp & 3;    // 0..3 -> 32 cols each
    const int bm = blockIdx.y;
    const int bn = blockIdx.x;

    const int8_t* gA = g_packedX + (size_t)(bm * BM) * IN_F;
    const int8_t* gB = g_packedW + (size_t)(bn * BN) * IN_F;

    int acc[4][4][4];
#pragma unroll
    for (int i = 0; i < 4; i++)
#pragma unroll
        for (int j = 0; j < 4; j++)
#pragma unroll
            for (int r = 0; r < 4; r++) acc[i][j][r] = 0;

    const int NK = IN_F / BK;   // 64 k-tiles

    // ---- async tile loader: 128 rows x 64B = 512 x 16B chunks per operand ----
    auto load_tile = [&](int buf, int kt) {
        const int k0 = kt * BK;
#pragma unroll
        for (int t = 0; t < 2; t++) {
            int id  = tid + t * THREADS;       // 0..511
            int row = id >> 2;
            int c   = id & 3;
            cp_async16(smem_u32(&sA[buf][row * SSTRIDE + c * 16]),
                       gA + (size_t)row * IN_F + k0 + c * 16);
            cp_async16(smem_u32(&sB[buf][row * SSTRIDE + c * 16]),
                       gB + (size_t)row * IN_F + k0 + c * 16);
        }
        asm volatile("cp.async.commit_group;\n" ::: "memory");
    };

    load_tile(0, 0);

    for (int kt = 0; kt < NK; kt++) {
        const int buf = kt & 1;
        if (kt + 1 < NK) {
            load_tile(buf ^ 1, kt + 1);
            asm volatile("cp.async.wait_group 1;\n" ::: "memory");
        } else {
            asm volatile("cp.async.wait_group 0;\n" ::: "memory");
        }
        __syncthreads();

        const int8_t* baseA = &sA[buf][0];
        const int8_t* baseB = &sB[buf][0];

#pragma unroll
        for (int ks = 0; ks < 2; ks++) {
            // A fragments: m16n8k32.s8 row-major layout
            uint32_t afr[4][4];
#pragma unroll
            for (int i = 0; i < 4; i++) {
                int row = warp_m * 64 + i * 16 + (lane >> 2);
                int kb  = ks * 32 + (lane & 3) * 4;
                afr[i][0] = *(const uint32_t*)(baseA + (row    ) * SSTRIDE + kb);
                afr[i][1] = *(const uint32_t*)(baseA + (row + 8) * SSTRIDE + kb);
                afr[i][2] = *(const uint32_t*)(baseA + (row    ) * SSTRIDE + kb + 16);
                afr[i][3] = *(const uint32_t*)(baseA + (row + 8) * SSTRIDE + kb + 16);
            }
            // B fragments: col-major (weight is [N,K] row-major = B^T)
            uint32_t bfr[4][2];
#pragma unroll
            for (int j = 0; j < 4; j++) {
                int nrow = warp_n * 32 + j * 8 + (lane >> 2);
                int kb   = ks * 32 + (lane & 3) * 4;
                bfr[j][0] = *(const uint32_t*)(baseB + nrow * SSTRIDE + kb);
                bfr[j][1] = *(const uint32_t*)(baseB + nrow * SSTRIDE + kb + 16);
            }
#pragma unroll
            for (int i = 0; i < 4; i++)
#pragma unroll
                for (int j = 0; j < 4; j++) {
                    asm volatile(
                        "mma.sync.aligned.m16n8k32.row.col.s32.s8.s8.s32 "
                        "{%0,%1,%2,%3}, {%4,%5,%6,%7}, {%8,%9}, {%0,%1,%2,%3};\n"
                        : "+r"(acc[i][j][0]), "+r"(acc[i][j][1]),
                          "+r"(acc[i][j][2]), "+r"(acc[i][j][3])
                        : "r"(afr[i][0]), "r"(afr[i][1]), "r"(afr[i][2]), "r"(afr[i][3]),
                          "r"(bfr[j][0]), "r"(bfr[j][1]));
                }
        }
        __syncthreads();
    }

    // ---- fused epilogue: dequant + bias + exact GeLU + requant, write as f32 ----
    const float a = *pa;
    const float b = *pb;

    const int row_base = bm * BM + warp_m * 64 + (lane >> 2);
    const int col_base = bn * BN + warp_n * 32 + (lane & 3) * 2;

#pragma unroll
    for (int i = 0; i < 4; i++) {
        const int row0 = row_base + i * 16;
#pragma unroll
        for (int j = 0; j < 4; j++) {
            const int col = col_base + j * 8;
            const float b0 = bias[col];
            const float b1 = bias[col + 1];

            float2 v0;
            v0.x = quantize_gelu(acc[i][j][0], b0, a, b);
            v0.y = quantize_gelu(acc[i][j][1], b1, a, b);
            *(float2*)&out[(size_t)row0 * OUT_F + col] = v0;

            float2 v1;
            v1.x = quantize_gelu(acc[i][j][2], b0, a, b);
            v1.y = quantize_gelu(acc[i][j][3], b1, a, b);
            *(float2*)&out[(size_t)(row0 + 8) * OUT_F + col] = v1;
        }
    }
}

extern "C" void kernel_launch(void* const* d_in, const int* in_sizes, int n_in,
                              void* d_out, int out_size)
{
    const int*   x    = (const int*)  d_in[0];   // int32-widened int8 values
    const int*   w    = (const int*)  d_in[1];   // int32-widened int8 values
    const float* bias = (const float*)d_in[2];
    const float* a    = (const float*)d_in[3];
    const float* b    = (const float*)d_in[4];
    float* out = (float*)d_out;

    int8_t* pX = nullptr;
    int8_t* pW = nullptr;
    cudaGetSymbolAddress((void**)&pX, g_packedX);
    cudaGetSymbolAddress((void**)&pW, g_packedW);

    // pack int32 -> int8 (4 elements per thread)
    {
        int nwx = (TOKENS * IN_F) / 4;
        pack_kernel<<<(nwx + 255) / 256, 256>>>(x, (uint32_t*)pX, nwx);
        int nww = (OUT_F * IN_F) / 4;
        pack_kernel<<<(nww + 255) / 256, 256>>>(w, (uint32_t*)pW, nww);
    }

    dim3 grid(OUT_F / BN, TOKENS / BM);   // (32, 64)
    w8a8_gelu_q_kernel<<<grid, THREADS>>>(bias, a, b, out);
}